// round 12
// baseline (speedup 1.0000x reference)
#include <cuda_runtime.h>
#include <cuda_fp16.h>

// 1M tasks x 40-step rollout -> scalar. R12: occupancy attack.
// R8==R11 (82.4us) with ~18% different instruction counts proved the kernel
// is STALL-bound (MUFU lat-16 chains, issue 46%, occ 33%), not pipe-bound.
// Fix: force 4 CTAs/SM (<=64 regs) to double resident warps 24->32/SM.
// Register diet: final error term computed from half2 regs (t0/t1 fp32
// copies die before the loop); all else identical to R11.

typedef unsigned int u32;

#define DT      0.05f
#define TPB     256
#define MAX_BLOCKS 4096

__device__ float g_part_err[MAX_BLOCKS];
__device__ float g_part_nor[MAX_BLOCKS];
__device__ unsigned int g_count = 0;

__device__ __forceinline__ __half2 tanh2(__half2 x) {
    u32 xu = *reinterpret_cast<u32*>(&x);
    u32 r;
    asm("tanh.approx.f16x2 %0, %1;" : "=r"(r) : "r"(xu));
    return *reinterpret_cast<__half2*>(&r);
}

__global__ void __launch_bounds__(TPB, 4)
rollout_kernel(const float* __restrict__ omega,
               const float* __restrict__ Wh1, const float* __restrict__ bh1,
               const float* __restrict__ Wh2, const float* __restrict__ bh2,
               const float* __restrict__ Wr1, const float* __restrict__ br1,
               const float* __restrict__ Wr2, const float* __restrict__ br2,
               const float* __restrict__ alpha,
               float* __restrict__ out,
               int N, int nblocks)
{
    const int gi = blockIdx.x * TPB + threadIdx.x;   // quad index
    const int base = 4 * gi;

    // ---- broadcast weights (half2 in-loop copies) ----
    __half2 Wc2h[4], Wc3h[4], W2h[4], BH2h;
    __half2 Wrh[9], Brh[3], Woh[3], Boh;
    {
        // fp32 staging values die before the main loop (register diet)
        float wc0[4], wc1[4], vb1[4];
#pragma unroll
        for (int k = 0; k < 4; k++) {
            wc0[k]  = __ldg(Wh1 + 4 * k + 0);
            wc1[k]  = __ldg(Wh1 + 4 * k + 1);
            Wc2h[k] = __float2half2_rn(__ldg(Wh1 + 4 * k + 2));
            Wc3h[k] = __float2half2_rn(__ldg(Wh1 + 4 * k + 3));
            vb1[k]  = __ldg(bh1 + k);
            W2h[k]  = __float2half2_rn(__ldg(Wh2 + k));
        }
        // stash for CH computation below
        #pragma unroll
        for (int k = 0; k < 4; k++) { Wh1 += 0; }   // no-op; keep scope clear
        BH2h = __float2half2_rn(__ldg(bh2));
#pragma unroll
        for (int k = 0; k < 9; k++) Wrh[k] = __float2half2_rn(__ldg(Wr1 + k));
#pragma unroll
        for (int k = 0; k < 3; k++) {
            Brh[k] = __float2half2_rn(__ldg(br1 + k));
            Woh[k] = __float2half2_rn(__ldg(Wr2 + k));
        }
        Boh = __float2half2_rn(__ldg(br2));

        // ---- per-task targets + per-chain constants (fp32 dies here) ----
        float t0[4], t1[4];
#pragma unroll
        for (int k = 0; k < 4; k++) { t0[k] = 0.0f; t1[k] = 0.0f; }
        if ((base + 3) < N && (N & 3) == 0) {
            float4 o0 = __ldg(reinterpret_cast<const float4*>(omega + base));
            t0[0] = o0.x; t0[1] = o0.y; t0[2] = o0.z; t0[3] = o0.w;
            float4 o1 = __ldg(reinterpret_cast<const float4*>(omega + N + base));
            t1[0] = o1.x; t1[1] = o1.y; t1[2] = o1.z; t1[3] = o1.w;
        } else {
#pragma unroll
            for (int k = 0; k < 4; k++) {
                if ((base + k) < N) {
                    t0[k] = __ldg(omega + base + k);
                    t1[k] = __ldg(omega + N + base + k);
                }
            }
        }
        extern __shared__ char dummy_smem[];   // (unused; keeps layout simple)
        // per-chain constants stored half2 (declared below, filled here)
        // -- declared after this block via goto-free structure: use globals of
        //    the enclosing scope instead:
        // (moved declarations up so they are assigned here)
        // CH / T0h / T1h are declared just below this block in outer scope.
        // To keep C++ scoping valid we compute into temporaries then copy.
        // Simplest: compute directly (declarations hoisted before this block
        // would be cleaner, but nvcc handles this fine as written below.)
        // --- see outer declarations ---
        // (fall through)
        // store into outer-scope arrays:
        {
            // nothing here; real assignment below
        }
        // NOTE: assignments happen right after this scope using t0/t1 which
        // we copy into 4+4 temporaries packed as half2 to avoid fp32 regs
        // escaping: pack now.
        __half2 t0h01 = __floats2half2_rn(t0[0], t0[1]);
        __half2 t0h23 = __floats2half2_rn(t0[2], t0[3]);
        __half2 t1h01 = __floats2half2_rn(t1[0], t1[1]);
        __half2 t1h23 = __floats2half2_rn(t1[2], t1[3]);
        // compute CH in fp32 then pack (t0,t1 still live inside this scope)
        __half2 ch0[4], ch1[4];
#pragma unroll
        for (int k = 0; k < 4; k++) {
            ch0[k] = __floats2half2_rn(fmaf(wc0[k], t0[0], fmaf(wc1[k], t1[0], vb1[k])),
                                       fmaf(wc0[k], t0[1], fmaf(wc1[k], t1[1], vb1[k])));
            ch1[k] = __floats2half2_rn(fmaf(wc0[k], t0[2], fmaf(wc1[k], t1[2], vb1[k])),
                                       fmaf(wc0[k], t0[3], fmaf(wc1[k], t1[3], vb1[k])));
        }
        // export to outer scope via statics? No — just shadow into outer vars:
        // outer declarations follow; use lambda-free direct init:
        __half2* CHo = nullptr; (void)CHo;
        // We'll simply declare the outer arrays here and keep the rest of the
        // kernel inside this scope to avoid copies.
        __half2 CH[2][4] = {{ch0[0], ch0[1], ch0[2], ch0[3]},
                            {ch1[0], ch1[1], ch1[2], ch1[3]}};
        __half2 T0h[2] = {t0h01, t0h23};
        __half2 T1h[2] = {t1h01, t1h23};

        const __half2 PT1h = __float2half2_rn(0.1f);
        const __half2 THRh = __float2half2_rn(0.01f);
        const __half2 DTh  = __float2half2_rn(DT);
        const __half2 Z2   = __float2half2_rn(0.0f);

        float mv[4];
#pragma unroll
        for (int k = 0; k < 4; k++) mv[k] = ((base + k) < N) ? 1.0f : 0.0f;

        __half2 S0h[2] = {Z2, Z2}, S1h[2] = {Z2, Z2};
        __half2 ERR0h[2] = {Z2, Z2}, ERR1h[2] = {Z2, Z2};
        __half2 NORh[2] = {Z2, Z2}, EFFh[2] = {Z2, Z2};
        float errT = 0.0f, norT = 0.0f;

#pragma unroll 1
        for (int ph = 0; ph < 5; ph++) {       // 5 phases x 8 steps = 40
#pragma unroll
            for (int st = 0; st < 8; st++) {
#pragma unroll
                for (int p = 0; p < 2; p++) {
                    __half2 e0 = __hsub2(T0h[p], S0h[p]);
                    __half2 e1 = __hsub2(T1h[p], S1h[p]);
                    ERR0h[p] = __hfma2(e0, e0, ERR0h[p]);   // x10 at flush
                    ERR1h[p] = __hfma2(e1, e1, ERR1h[p]);

                    __half2 H0 = tanh2(__hfma2(Wc2h[0], S0h[p], __hfma2(Wc3h[0], S1h[p], CH[p][0])));
                    __half2 H1 = tanh2(__hfma2(Wc2h[1], S0h[p], __hfma2(Wc3h[1], S1h[p], CH[p][1])));
                    __half2 H2 = tanh2(__hfma2(Wc2h[2], S0h[p], __hfma2(Wc3h[2], S1h[p], CH[p][2])));
                    __half2 H3 = tanh2(__hfma2(Wc2h[3], S0h[p], __hfma2(Wc3h[3], S1h[p], CH[p][3])));
                    __half2 Z  = tanh2(__hfma2(W2h[0], H0, __hfma2(W2h[1], H1,
                                       __hfma2(W2h[2], H2, __hfma2(W2h[3], H3, BH2h)))));

                    __half2 R0 = tanh2(__hfma2(Wrh[0], S0h[p], __hfma2(Wrh[1], S1h[p], __hfma2(Wrh[2], Z, Brh[0]))));
                    __half2 R1 = tanh2(__hfma2(Wrh[3], S0h[p], __hfma2(Wrh[4], S1h[p], __hfma2(Wrh[5], Z, Brh[1]))));
                    __half2 R2 = tanh2(__hfma2(Wrh[6], S0h[p], __hfma2(Wrh[7], S1h[p], __hfma2(Wrh[8], Z, Brh[2]))));
                    __half2 Ah = __hfma2(Woh[0], R0, __hfma2(Woh[1], R1, __hfma2(Woh[2], R2, Boh)));

                    // divergence: d = (e0 - z) + 0.1*e1
                    __half2 d = __hfma2(PT1h, e1, __hsub2(e0, Z));
                    NORh[p] = __hfma2(d, d, NORh[p]);

                    // effort: |z| > 0.01
                    EFFh[p] = __hadd2(EFFh[p], __hgt2(__habs2(Z), THRh));

                    // dynamics
                    __half2 nS0 = __hfma2(DTh, S1h[p], S0h[p]);
                    S1h[p] = __hfma2(DTh, Ah, S1h[p]);
                    S0h[p] = nS0;
                }
            }
            // flush to fp32 (mask-folded; x10 applied here)
#pragma unroll
            for (int p = 0; p < 2; p++) {
                float2 e0f = __half22float2(ERR0h[p]);
                float2 e1f = __half22float2(ERR1h[p]);
                float2 nf  = __half22float2(NORh[p]);
                errT = fmaf(mv[2*p],   fmaf(10.0f, e0f.x, e1f.x),
                       fmaf(mv[2*p+1], fmaf(10.0f, e0f.y, e1f.y), errT));
                norT = fmaf(mv[2*p], nf.x, fmaf(mv[2*p+1], nf.y, norT));
                ERR0h[p] = Z2; ERR1h[p] = Z2; NORh[p] = Z2;
            }
        }

        // final error term on s_40 (half2 math; same noise class as loop)
        float sumA = errT, sumB = norT;
#pragma unroll
        for (int p = 0; p < 2; p++) {
            __half2 e0 = __hsub2(T0h[p], S0h[p]);
            __half2 e1 = __hsub2(T1h[p], S1h[p]);
            float2 e0f = __half22float2(e0);
            float2 e1f = __half22float2(e1);
            float2 ev  = __half22float2(EFFh[p]);
            float fin = fmaf(10.0f * e0f.x, e0f.x, e1f.x * e1f.x);
            sumA = fmaf(mv[2*p], fin + ev.x, sumA);
            fin = fmaf(10.0f * e0f.y, e0f.y, e1f.y * e1f.y);
            sumA = fmaf(mv[2*p+1], fin + ev.y, sumA);
        }

        // ---- block reduce ----
#pragma unroll
        for (int off = 16; off > 0; off >>= 1) {
            sumA += __shfl_down_sync(0xFFFFFFFFu, sumA, off);
            sumB += __shfl_down_sync(0xFFFFFFFFu, sumB, off);
        }
        __shared__ float shA[TPB / 32];
        __shared__ float shB[TPB / 32];
        const int lane = threadIdx.x & 31;
        const int wid  = threadIdx.x >> 5;
        if (lane == 0) { shA[wid] = sumA; shB[wid] = sumB; }
        __syncthreads();
        if (wid == 0) {
            sumA = (lane < TPB / 32) ? shA[lane] : 0.0f;
            sumB = (lane < TPB / 32) ? shB[lane] : 0.0f;
#pragma unroll
            for (int off = (TPB / 64); off > 0; off >>= 1) {
                sumA += __shfl_down_sync(0xFFFFFFFFu, sumA, off);
                sumB += __shfl_down_sync(0xFFFFFFFFu, sumB, off);
            }
            if (lane == 0) {
                g_part_err[blockIdx.x] = sumA;
                g_part_nor[blockIdx.x] = sumB;
            }
        }
    }

    // ---- last-block deterministic final reduction ----
    __shared__ unsigned int s_is_last;
    __threadfence();
    if (threadIdx.x == 0) {
        unsigned int old = atomicAdd(&g_count, 1u);
        s_is_last = (old == (unsigned int)(nblocks - 1)) ? 1u : 0u;
    }
    __syncthreads();

    if (s_is_last) {
        __shared__ double dA[TPB];
        __shared__ double dB[TPB];
        double a = 0.0, b = 0.0;
        for (int k = threadIdx.x; k < nblocks; k += TPB) {
            a += (double)__ldcg(&g_part_err[k]);
            b += (double)__ldcg(&g_part_nor[k]);
        }
        dA[threadIdx.x] = a;
        dB[threadIdx.x] = b;
        __syncthreads();
#pragma unroll
        for (int s = TPB / 2; s > 0; s >>= 1) {
            if (threadIdx.x < s) {
                dA[threadIdx.x] += dA[threadIdx.x + s];
                dB[threadIdx.x] += dB[threadIdx.x + s];
            }
            __syncthreads();
        }
        if (threadIdx.x == 0) {
            double invN = 1.0 / (double)N;
            out[0] = (float)(dA[0] * invN + (double)__ldg(alpha) * (dB[0] * invN));
            g_count = 0;   // reset for next graph replay
        }
    }
}

extern "C" void kernel_launch(void* const* d_in, const int* in_sizes, int n_in,
                              void* d_out, int out_size)
{
    // metadata order: omega, Wh1, bh1, Wh2, bh2, Wr1, br1, Wr2, br2, alpha, n_tasks
    const float* omega = (const float*)d_in[0];
    const float* Wh1   = (const float*)d_in[1];
    const float* bh1   = (const float*)d_in[2];
    const float* Wh2   = (const float*)d_in[3];
    const float* bh2   = (const float*)d_in[4];
    const float* Wr1   = (const float*)d_in[5];
    const float* br1   = (const float*)d_in[6];
    const float* Wr2   = (const float*)d_in[7];
    const float* br2   = (const float*)d_in[8];
    const float* alpha = (const float*)d_in[9];

    const int N = in_sizes[0] / 2;                 // omega is [2, N]
    const int nquads = (N + 3) / 4;                // 4 tasks per thread
    int nblocks = (nquads + TPB - 1) / TPB;        // N=1M -> 1024
    if (nblocks > MAX_BLOCKS) nblocks = MAX_BLOCKS;

    rollout_kernel<<<nblocks, TPB, 8>>>(omega, Wh1, bh1, Wh2, bh2,
                                        Wr1, br1, Wr2, br2, alpha,
                                        (float*)d_out, N, nblocks);
}